// round 13
// baseline (speedup 1.0000x reference)
#include <cuda_runtime.h>
#include <cuda_fp16.h>
#include <math.h>
#include <stdint.h>

// ---------------- problem constants ----------------
#define BATCH   32
#define HW      56
#define DIM     256
#define WS      7
#define SHIFT   3
#define NH      8
#define HD      32
#define NTOK    49
#define NWIN    64
#define BW      (BATCH*NWIN)
#define MTOK    (BATCH*HW*HW)   // 100352
#define SCALE   0.17677669529663687f

// ---------------- scratch ----------------
__device__ __half hb_a  [(size_t)MTOK * 256];
__device__ __half hb_qkv[(size_t)MTOK * 768];
__device__ __half hb_h1 [(size_t)MTOK * 1024];
__device__ float  g_xres[(size_t)MTOK * 256];
__device__ __half g_biasM[4 * NH * NTOK * NTOK];
__device__ __half hw_qkv [768 * 256];
__device__ __half hw_proj[256 * 256];
__device__ __half hw_fc1 [1024 * 256];
__device__ __half hw_fc2 [256 * 1024];

// ---------------- PTX helpers ----------------
__device__ __forceinline__ uint32_t cvta_s(const void* p) {
    uint32_t a;
    asm("{ .reg .u64 t; cvta.to.shared.u64 t, %1; cvt.u32.u64 %0, t; }" : "=r"(a) : "l"(p));
    return a;
}
__device__ __forceinline__ void ldsm_x4(unsigned* r, uint32_t a) {
    asm volatile("ldmatrix.sync.aligned.m8n8.x4.shared.b16 {%0,%1,%2,%3}, [%4];"
        : "=r"(r[0]), "=r"(r[1]), "=r"(r[2]), "=r"(r[3]) : "r"(a));
}
__device__ __forceinline__ void ldsm_x2(unsigned* r, uint32_t a) {
    asm volatile("ldmatrix.sync.aligned.m8n8.x2.shared.b16 {%0,%1}, [%2];"
        : "=r"(r[0]), "=r"(r[1]) : "r"(a));
}
#define CP_ASYNC16(dst, src) asm volatile("cp.async.ca.shared.global [%0], [%1], 16;" :: "r"(dst), "l"(src))
#define CP_COMMIT()          asm volatile("cp.async.commit_group;" ::: "memory")
#define CP_WAIT1()           asm volatile("cp.async.wait_group 1;" ::: "memory")
#define CP_WAIT0()           asm volatile("cp.async.wait_group 0;" ::: "memory")

__device__ __forceinline__ void mma_f16(float* c, const unsigned* a, const unsigned* b) {
    asm("mma.sync.aligned.m16n8k16.row.col.f32.f16.f16.f32 "
        "{%0,%1,%2,%3},{%4,%5,%6,%7},{%8,%9},{%0,%1,%2,%3};"
        : "+f"(c[0]), "+f"(c[1]), "+f"(c[2]), "+f"(c[3])
        : "r"(a[0]), "r"(a[1]), "r"(a[2]), "r"(a[3]), "r"(b[0]), "r"(b[1]));
}

// ---------------- all weights fp32 -> fp16, one kernel ----------------
#define NW0 (768*256)
#define NW1 (256*256)
#define NW2 (1024*256)
#define NW3 (256*1024)
__global__ void wconv_all(const float* __restrict__ w0, __half* __restrict__ o0,
                          const float* __restrict__ w1, __half* __restrict__ o1,
                          const float* __restrict__ w2, __half* __restrict__ o2,
                          const float* __restrict__ w3, __half* __restrict__ o3)
{
    int i = blockIdx.x * 256 + threadIdx.x;
    if (i < NW0) { o0[i] = __float2half(w0[i]); return; }
    i -= NW0;
    if (i < NW1) { o1[i] = __float2half(w1[i]); return; }
    i -= NW1;
    if (i < NW2) { o2[i] = __float2half(w2[i]); return; }
    i -= NW2;
    if (i < NW3) { o3[i] = __float2half(w3[i]); }
}

// ---------------- masked rel-pos bias table ----------------
__global__ void biasm_kernel(const float* __restrict__ rel_table, __half* __restrict__ bm)
{
    int i = blockIdx.x * 256 + threadIdx.x;
    if (i >= 4 * NH * NTOK * NTOK) return;
    int type = i / (NH * NTOK * NTOK);
    int rem  = i % (NH * NTOK * NTOK);
    int h = rem / (NTOK * NTOK);
    int s = rem % (NTOK * NTOK);
    int n = s / NTOK, m = s % NTOK;
    int rn = n / 7, cn = n % 7, rm = m / 7, cm = m % 7;
    int idx = (rn - rm + 6) * 13 + (cn - cm + 6);
    float v = rel_table[idx * NH + h];
    int th = type >> 1, tw = type & 1;
    int rhn = th ? (rn < 4 ? 1 : 2) : 0;
    int rwn = tw ? (cn < 4 ? 1 : 2) : 0;
    int rhm = th ? (rm < 4 ? 1 : 2) : 0;
    int rwm = tw ? (cm < 4 ? 1 : 2) : 0;
    if (rhn * 3 + rwn != rhm * 3 + rwm) v -= 100.f;
    bm[i] = __float2half(v);
}

// ---------------- LayerNorm: one row per warp, float4 I/O ----------------
template<int PERM>
__global__ void __launch_bounds__(256) ln_kernel(
    const float* __restrict__ in, __half* __restrict__ out,
    const float* __restrict__ gam, const float* __restrict__ bet)
{
    const int row = blockIdx.x * 8 + (threadIdx.x >> 5);
    const int lane = threadIdx.x & 31;
    int src;
    if (PERM) {
        int bw = row / NTOK, t = row % NTOK;
        int b = bw >> 6, w = bw & 63;
        int wh = w >> 3, ww = w & 7;
        int r = t / 7, c = t % 7;
        int gh = wh * 7 + r + SHIFT; if (gh >= HW) gh -= HW;
        int gw = ww * 7 + c + SHIFT; if (gw >= HW) gw -= HW;
        src = (b * (HW*HW) + gh * HW + gw) * DIM;
    } else {
        src = row * DIM;
    }
    const int col = lane * 8;
    float4 v0 = *(const float4*)&in[src + col];
    float4 v1 = *(const float4*)&in[src + col + 4];

    float s = v0.x+v0.y+v0.z+v0.w + v1.x+v1.y+v1.z+v1.w;
    float q = v0.x*v0.x+v0.y*v0.y+v0.z*v0.z+v0.w*v0.w
            + v1.x*v1.x+v1.y*v1.y+v1.z*v1.z+v1.w*v1.w;
    #pragma unroll
    for (int o = 16; o > 0; o >>= 1) {
        s += __shfl_xor_sync(0xFFFFFFFFu, s, o);
        q += __shfl_xor_sync(0xFFFFFFFFu, q, o);
    }
    float mu = s * (1.0f/DIM);
    float rstd = rsqrtf(q * (1.0f/DIM) - mu*mu + 1e-5f);

    float4 g0 = *(const float4*)&gam[col], g1 = *(const float4*)&gam[col+4];
    float4 b0 = *(const float4*)&bet[col], b1 = *(const float4*)&bet[col+4];

    uint4 o8;
    ((__half2*)&o8)[0] = __floats2half2_rn((v0.x-mu)*rstd*g0.x+b0.x, (v0.y-mu)*rstd*g0.y+b0.y);
    ((__half2*)&o8)[1] = __floats2half2_rn((v0.z-mu)*rstd*g0.z+b0.z, (v0.w-mu)*rstd*g0.w+b0.w);
    ((__half2*)&o8)[2] = __floats2half2_rn((v1.x-mu)*rstd*g1.x+b1.x, (v1.y-mu)*rstd*g1.y+b1.y);
    ((__half2*)&o8)[3] = __floats2half2_rn((v1.z-mu)*rstd*g1.z+b1.z, (v1.w-mu)*rstd*g1.w+b1.w);
    *(uint4*)&out[(size_t)row * DIM + col] = o8;
}

// ---------------- fp16 GEMM: 4 warps, warp tile 64x64, cp.async 3-stage ----
#define STG_H    (128 * 40)
#define STG_B    (STG_H * 2)
#define GSMEM    (6 * STG_B)   // 61440 B

template<int EPI>
__global__ void __launch_bounds__(128, 2) hgemm(
    const __half* __restrict__ A, const __half* __restrict__ B,
    const float* __restrict__ bias, float* __restrict__ Cf, __half* __restrict__ Ch,
    const float* __restrict__ res, int M, int Nn, int K)
{
    extern __shared__ __half dsm[];

    const int tid = threadIdx.x;
    const int lane = tid & 31, wid = tid >> 5;
    const int wm = wid >> 1, wn = wid & 1;
    const int gid = lane >> 2, tig = lane & 3;
    const int m0 = blockIdx.y * 128, n0 = blockIdx.x * 128;

    const uint32_t sbase = cvta_s(dsm);
    const uint32_t sA = sbase;
    const uint32_t sB = sbase + 3 * STG_B;

    const int lr0 = tid >> 2, lq0 = tid & 3;

    float c[4][8][4];
    #pragma unroll
    for (int i = 0; i < 4; i++)
        #pragma unroll
        for (int j = 0; j < 8; j++)
            #pragma unroll
            for (int r = 0; r < 4; r++) c[i][j][r] = 0.f;

    const int nk = K >> 5;

    const uint32_t a_off = ((uint32_t)(wm * 64 + (lane & 15)) * 40 + (lane >> 4) * 8) * 2;
    const uint32_t b_off = ((uint32_t)(wn * 64 + ((lane >> 4) & 1) * 8 + (lane & 7)) * 40
                           + ((lane >> 3) & 1) * 8) * 2;

    auto issue = [&](int kt, int stg) {
        const size_t kb = (size_t)kt * 32 + lq0 * 8;
        #pragma unroll
        for (int s = 0; s < 4; s++) {
            int row = lr0 + 32 * s;
            uint32_t dA = sA + stg * STG_B + (row * 40 + lq0 * 8) * 2;
            uint32_t dB = sB + stg * STG_B + (row * 40 + lq0 * 8) * 2;
            CP_ASYNC16(dA, &A[(size_t)(m0 + row) * K + kb]);
            CP_ASYNC16(dB, &B[(size_t)(n0 + row) * K + kb]);
        }
        CP_COMMIT();
    };

    issue(0, 0);
    issue(1, 1);

    for (int kt = 0; kt < nk; kt++) {
        const int stg = kt % 3;
        if (kt + 2 < nk) { CP_WAIT1(); } else { CP_WAIT0(); }
        __syncthreads();
        if (kt + 2 < nk) issue(kt + 2, (kt + 2) % 3);

        const uint32_t aS = sA + stg * STG_B + a_off;
        const uint32_t bS = sB + stg * STG_B + b_off;
        #pragma unroll
        for (int kk = 0; kk < 2; kk++) {
            unsigned af[4][4], bf[8][2];
            #pragma unroll
            for (int mt = 0; mt < 4; mt++)
                ldsm_x4(af[mt], aS + (mt * 16 * 40 + kk * 16) * 2);
            #pragma unroll
            for (int p = 0; p < 4; p++) {
                unsigned br[4];
                ldsm_x4(br, bS + (p * 16 * 40 + kk * 16) * 2);
                bf[2*p][0]   = br[0]; bf[2*p][1]   = br[1];
                bf[2*p+1][0] = br[2]; bf[2*p+1][1] = br[3];
            }
            #pragma unroll
            for (int mt = 0; mt < 4; mt++)
                #pragma unroll
                for (int nt = 0; nt < 8; nt++)
                    mma_f16(c[mt][nt], af[mt], bf[nt]);
        }
    }

    // ---------------- epilogue ----------------
    if (EPI == 0 || EPI == 1) {
        __half* sC = dsm;
        const int srow = wm * 16 + gid;
        const int scol = wn * 64 + 2 * tig;
        #pragma unroll
        for (int mt = 0; mt < 4; mt++) {
            __syncthreads();
            #pragma unroll
            for (int nt = 0; nt < 8; nt++) {
                int cb = n0 + wn * 64 + nt * 8 + 2 * tig;
                float bs0 = bias[cb], bs1 = bias[cb + 1];
                float v00 = c[mt][nt][0] + bs0, v01 = c[mt][nt][1] + bs1;
                float v10 = c[mt][nt][2] + bs0, v11 = c[mt][nt][3] + bs1;
                if (EPI == 0) {
                    if (cb < 256) { v00 *= SCALE; v01 *= SCALE; v10 *= SCALE; v11 *= SCALE; }
                } else {
                    const float kk = 0.70710678118654752f;
                    v00 = 0.5f * v00 * (1.f + erff(v00 * kk));
                    v01 = 0.5f * v01 * (1.f + erff(v01 * kk));
                    v10 = 0.5f * v10 * (1.f + erff(v10 * kk));
                    v11 = 0.5f * v11 * (1.f + erff(v11 * kk));
                }
                *(__half2*)&sC[(srow    ) * 136 + scol + nt * 8] = __floats2half2_rn(v00, v01);
                *(__half2*)&sC[(srow + 8) * 136 + scol + nt * 8] = __floats2half2_rn(v10, v11);
            }
            __syncthreads();
            #pragma unroll
            for (int s = 0; s < 4; s++) {
                int idx = tid + s * 128;
                int sr = idx >> 4, c8 = (idx & 15) * 8;
                int grow = m0 + (sr >> 4) * 64 + mt * 16 + (sr & 15);
                uint4 val = *(uint4*)&sC[sr * 136 + c8];
                *(uint4*)&Ch[(size_t)grow * Nn + n0 + c8] = val;
            }
        }
    } else {
        #pragma unroll
        for (int mt = 0; mt < 4; mt++) {
            #pragma unroll
            for (int nt = 0; nt < 8; nt++) {
                int r0 = m0 + wm * 64 + mt * 16 + gid;
                int r1 = r0 + 8;
                int cb = n0 + wn * 64 + nt * 8 + 2 * tig;
                float bs0 = bias[cb], bs1 = bias[cb + 1];
                float v00 = c[mt][nt][0] + bs0, v01 = c[mt][nt][1] + bs1;
                float v10 = c[mt][nt][2] + bs0, v11 = c[mt][nt][3] + bs1;

                if (EPI == 2) {
                    #pragma unroll
                    for (int rr = 0; rr < 2; rr++) {
                        int m = rr ? r1 : r0;
                        float va = rr ? v10 : v00, vb = rr ? v11 : v01;
                        int bw = m / NTOK, t = m % NTOK;
                        int b = bw >> 6, w = bw & 63;
                        int wh = w >> 3, ww = w & 7;
                        int r = t / 7, cc = t % 7;
                        int gh = wh * 7 + r + SHIFT; if (gh >= HW) gh -= HW;
                        int gw = ww * 7 + cc + SHIFT; if (gw >= HW) gw -= HW;
                        size_t dst = (size_t)(b * (HW*HW) + gh * HW + gw) * DIM + cb;
                        float2 rv = *(const float2*)&res[dst];
                        *(float2*)&Cf[dst] = make_float2(va + rv.x, vb + rv.y);
                    }
                } else {
                    size_t d0 = (size_t)r0 * Nn + cb, d1 = (size_t)r1 * Nn + cb;
                    float2 ra = *(const float2*)&res[d0];
                    float2 rb2 = *(const float2*)&res[d1];
                    *(float2*)&Cf[d0] = make_float2(v00 + ra.x, v01 + ra.y);
                    *(float2*)&Cf[d1] = make_float2(v10 + rb2.x, v11 + rb2.y);
                }
            }
        }
    }
}

// ---------------- tensor-core attention (ldmatrix fragment loads) ----------
__global__ void __launch_bounds__(256) attn_kernel(
    const __half* __restrict__ qkv, const __half* __restrict__ biasM,
    __half* __restrict__ out)
{
    __shared__ __half sQ [64][40];
    __shared__ __half sK [56][40];
    __shared__ __half sVT[32][72];
    __shared__ float  sS [64][60];

    __half (*sP)[120] = reinterpret_cast<__half(*)[120]>(sS);

    const int bw = blockIdx.x >> 3;
    const int h  = blockIdx.x & 7;
    const int tid = threadIdx.x, lane = tid & 31, wid = tid >> 5;
    const int gid = lane >> 2, tig = lane & 3;

    const int w = bw & 63;
    const int type = (((w >> 3) == 7) ? 2 : 0) + (((w & 7) == 7) ? 1 : 0);
    const __half* bm = biasM + ((size_t)(type * NH + h)) * (NTOK * NTOK);

    for (int i = tid; i < 32 * 36; i += 256) ((uint32_t*)sVT)[i] = 0;

    for (int i = tid; i < NTOK * 4; i += 256) {
        int n = i >> 2, d8 = (i & 3) * 8;
        size_t basep = (size_t)(bw * NTOK + n) * 768 + h * HD + d8;
        uint4 qu = *(const uint4*)&qkv[basep];
        uint4 ku = *(const uint4*)&qkv[basep + 256];
        uint4 vu = *(const uint4*)&qkv[basep + 512];
        *(uint4*)&sQ[n][d8] = qu;
        *(uint4*)&sK[n][d8] = ku;
        const __half* vh = (const __half*)&vu;
        #pragma unroll
        for (int j = 0; j < 8; j++) sVT[d8 + j][n] = vh[j];
    }
    __syncthreads();

    // ldmatrix per-lane offsets (halves*2 = bytes), mirrors hgemm patterns
    const uint32_t qBase = cvta_s(sQ)  + ((uint32_t)(lane & 15) * 40 + (lane >> 4) * 8) * 2;
    const uint32_t kBase = cvta_s(sK)  + ((uint32_t)(lane & 7)  * 40 + ((lane >> 3) & 1) * 8) * 2;
    const uint32_t pBase = cvta_s(sS)  + ((uint32_t)(lane & 15) * 120 + (lane >> 4) * 8) * 2;
    const uint32_t vBase = cvta_s(sVT) + ((uint32_t)(lane & 7)  * 72 + ((lane >> 3) & 1) * 8) * 2;

    // ---- QK^T: 28 tiles via ldmatrix ----
    for (int t = wid; t < 28; t += 8) {
        int mt = t & 3, nt = t >> 2;
        int rb = mt * 16, nb = nt * 8;
        float c[4] = {0.f, 0.f, 0.f, 0.f};
        #pragma unroll
        for (int ks = 0; ks < 2; ks++) {
            unsigned a[4], b[2];
            ldsm_x4(a, qBase + (rb * 40 + ks * 16) * 2);
            ldsm_x2(b, kBase + (nb * 40 + ks * 16) * 2);
            mma_f16(c, a, b);
        }
        sS[rb + gid    ][nb + 2*tig]     = c[0];
        sS[rb + gid    ][nb + 2*tig + 1] = c[1];
        sS[rb + gid + 8][nb + 2*tig]     = c[2];
        sS[rb + gid + 8][nb + 2*tig + 1] = c[3];
    }
    __syncthreads();

    // ---- softmax (warp per row); fp16 P overlaid on sS rows ----
    bool has1 = lane < (NTOK - 32);
    int m1c = has1 ? lane + 32 : lane;

    for (int n = wid; n < NTOK; n += 8) {
        float a0 = sS[n][lane] + __half2float(bm[n * NTOK + lane]);
        float a1 = has1 ? (sS[n][m1c] + __half2float(bm[n * NTOK + m1c])) : -1e30f;

        float mx = fmaxf(a0, a1);
        #pragma unroll
        for (int o = 16; o > 0; o >>= 1) mx = fmaxf(mx, __shfl_xor_sync(0xFFFFFFFFu, mx, o));
        float e0 = __expf(a0 - mx);
        float e1 = has1 ? __expf(a1 - mx) : 0.f;
        float sm = e0 + e1;
        #pragma unroll
        for (int o = 16; o > 0; o >>= 1) sm += __shfl_xor_sync(0xFFFFFFFFu, sm, o);
        float inv = 1.f / sm;
        __syncwarp();
        sP[n][lane]      = __float2half(e0 * inv);
        sP[n][lane + 32] = has1 ? __float2half(e1 * inv) : __half(0.f);
    }
    // rows 49..63 of P are read by PV fragments: zero them (cols 0..63)
    for (int i = tid; i < (64 - NTOK) * 32; i += 256) {
        int n = NTOK + (i >> 5), cc = (i & 31) * 2;
        *(__half2*)&sP[n][cc] = __half2(__half(0.f), __half(0.f));
    }
    __syncthreads();

    // ---- PV: 16 tiles via ldmatrix ----
    for (int t = wid; t < 16; t += 8) {
        int mt = t & 3, nt = t >> 2;
        int rb = mt * 16, nb = nt * 8;
        float c[4] = {0.f, 0.f, 0.f, 0.f};
        #pragma unroll
        for (int ks = 0; ks < 4; ks++) {
            unsigned a[4], b[2];
            ldsm_x4(a, pBase + (rb * 120 + ks * 16) * 2);
            ldsm_x2(b, vBase + (nb * 72 + ks * 16) * 2);
            mma_f16(c, a, b);
        }
        int n0 = rb + gid, n1 = n0 + 8;
        int d = nb + 2 * tig;
        if (n0 < NTOK)
            *(__half2*)&out[(size_t)(bw * NTOK + n0) * 256 + h * HD + d] =
                __floats2half2_rn(c[0], c[1]);
        if (n1 < NTOK)
            *(__half2*)&out[(size_t)(bw * NTOK + n1) * 256 + h * HD + d] =
                __floats2half2_rn(c[2], c[3]);
    }
}

// ---------------- launcher ----------------
extern "C" void kernel_launch(void* const* d_in, const int* in_sizes, int n_in,
                              void* d_out, int out_size)
{
    (void)in_sizes; (void)n_in; (void)out_size;
    const float* x        = (const float*)d_in[0];
    const float* norm1_g  = (const float*)d_in[1];
    const float* norm1_b  = (const float*)d_in[2];
    const float* qkv_w    = (const float*)d_in[3];
    const float* qkv_b    = (const float*)d_in[4];
    const float* rel_tab  = (const float*)d_in[5];
    const float* proj_w   = (const float*)d_in[6];
    const float* proj_b   = (const float*)d_in[7];
    const float* norm2_g  = (const float*)d_in[8];
    const float* norm2_b  = (const float*)d_in[9];
    const float* fc1_w    = (const float*)d_in[10];
    const float* fc1_b    = (const float*)d_in[11];
    const float* fc2_w    = (const float*)d_in[12];
    const float* fc2_b    = (const float*)d_in[13];
    float* out = (float*)d_out;

    __half *p_a, *p_qkv, *p_h1, *p_wqkv, *p_wproj, *p_wfc1, *p_wfc2, *p_biasM;
    float *p_xres;
    cudaGetSymbolAddress((void**)&p_a,     hb_a);
    cudaGetSymbolAddress((void**)&p_qkv,   hb_qkv);
    cudaGetSymbolAddress((void**)&p_h1,    hb_h1);
    cudaGetSymbolAddress((void**)&p_xres,  g_xres);
    cudaGetSymbolAddress((void**)&p_biasM, g_biasM);
    cudaGetSymbolAddress((void**)&p_wqkv,  hw_qkv);
    cudaGetSymbolAddress((void**)&p_wproj, hw_proj);
    cudaGetSymbolAddress((void**)&p_wfc1,  hw_fc1);
    cudaGetSymbolAddress((void**)&p_wfc2,  hw_fc2);

    cudaFuncSetAttribute(hgemm<0>, cudaFuncAttributeMaxDynamicSharedMemorySize, GSMEM);
    cudaFuncSetAttribute(hgemm<1>, cudaFuncAttributeMaxDynamicSharedMemorySize, GSMEM);
    cudaFuncSetAttribute(hgemm<2>, cudaFuncAttributeMaxDynamicSharedMemorySize, GSMEM);
    cudaFuncSetAttribute(hgemm<3>, cudaFuncAttributeMaxDynamicSharedMemorySize, GSMEM);

    const int M = MTOK;

    // #1: all weight conversions
    wconv_all<<<(NW0 + NW1 + NW2 + NW3 + 255)/256, 256>>>(
        qkv_w, p_wqkv, proj_w, p_wproj, fc1_w, p_wfc1, fc2_w, p_wfc2);
    // #2: masked bias table
    biasm_kernel<<<(4*NH*NTOK*NTOK + 255)/256, 256>>>(rel_tab, p_biasM);
    // #3: LN1
    ln_kernel<1><<<M/8, 256>>>(x, p_a, norm1_g, norm1_b);
    // #4 (profiled): qkv gemm
    hgemm<0><<<dim3(768/128, M/128), 128, GSMEM>>>(p_a, p_wqkv, qkv_b, nullptr, p_qkv, nullptr, M, 768, 256);
    // #5: attention
    attn_kernel<<<BW * NH, 256>>>(p_qkv, p_biasM, p_a);
    // #6: proj
    hgemm<2><<<dim3(256/128, M/128), 128, GSMEM>>>(p_a, p_wproj, proj_b, p_xres, nullptr, x, M, 256, 256);
    // #7: LN2
    ln_kernel<0><<<M/8, 256>>>(p_xres, p_a, norm2_g, norm2_b);
    // #8: fc1
    hgemm<1><<<dim3(1024/128, M/128), 128, GSMEM>>>(p_a, p_wfc1, fc1_b, nullptr, p_h1, nullptr, M, 1024, 256);
    // #9: fc2
    hgemm<3><<<dim3(256/128, M/128), 128, GSMEM>>>(p_h1, p_wfc2, fc2_b, out, nullptr, p_xres, M, 256, 1024);
}

// round 14
// speedup vs baseline: 1.0175x; 1.0175x over previous
#include <cuda_runtime.h>
#include <cuda_fp16.h>
#include <math.h>
#include <stdint.h>

// ---------------- problem constants ----------------
#define BATCH   32
#define HW      56
#define DIM     256
#define WS      7
#define SHIFT   3
#define NH      8
#define HD      32
#define NTOK    49
#define NWIN    64
#define BW      (BATCH*NWIN)
#define MTOK    (BATCH*HW*HW)   // 100352
#define SCALE   0.17677669529663687f

// ---------------- scratch ----------------
__device__ __half hb_a  [(size_t)MTOK * 256];
__device__ __half hb_qkv[(size_t)MTOK * 768];
__device__ __half hb_h1 [(size_t)MTOK * 1024];
__device__ float  g_xres[(size_t)MTOK * 256];
__device__ __half g_biasM[4 * NH * NTOK * NTOK];
__device__ __half hw_qkv [768 * 256];
__device__ __half hw_proj[256 * 256];
__device__ __half hw_fc1 [1024 * 256];
__device__ __half hw_fc2 [256 * 1024];

// ---------------- PTX helpers ----------------
__device__ __forceinline__ uint32_t cvta_s(const void* p) {
    uint32_t a;
    asm("{ .reg .u64 t; cvta.to.shared.u64 t, %1; cvt.u32.u64 %0, t; }" : "=r"(a) : "l"(p));
    return a;
}
__device__ __forceinline__ void ldsm_x4(unsigned* r, uint32_t a) {
    asm volatile("ldmatrix.sync.aligned.m8n8.x4.shared.b16 {%0,%1,%2,%3}, [%4];"
        : "=r"(r[0]), "=r"(r[1]), "=r"(r[2]), "=r"(r[3]) : "r"(a));
}
#define CP_ASYNC16(dst, src) asm volatile("cp.async.ca.shared.global [%0], [%1], 16;" :: "r"(dst), "l"(src))
#define CP_COMMIT()          asm volatile("cp.async.commit_group;" ::: "memory")
#define CP_WAIT1()           asm volatile("cp.async.wait_group 1;" ::: "memory")
#define CP_WAIT0()           asm volatile("cp.async.wait_group 0;" ::: "memory")

__device__ __forceinline__ void mma_f16(float* c, const unsigned* a, const unsigned* b) {
    asm("mma.sync.aligned.m16n8k16.row.col.f32.f16.f16.f32 "
        "{%0,%1,%2,%3},{%4,%5,%6,%7},{%8,%9},{%0,%1,%2,%3};"
        : "+f"(c[0]), "+f"(c[1]), "+f"(c[2]), "+f"(c[3])
        : "r"(a[0]), "r"(a[1]), "r"(a[2]), "r"(a[3]), "r"(b[0]), "r"(b[1]));
}

// ---------------- all weights fp32 -> fp16, one kernel ----------------
#define NW0 (768*256)
#define NW1 (256*256)
#define NW2 (1024*256)
#define NW3 (256*1024)
__global__ void wconv_all(const float* __restrict__ w0, __half* __restrict__ o0,
                          const float* __restrict__ w1, __half* __restrict__ o1,
                          const float* __restrict__ w2, __half* __restrict__ o2,
                          const float* __restrict__ w3, __half* __restrict__ o3)
{
    int i = blockIdx.x * 256 + threadIdx.x;
    if (i < NW0) { o0[i] = __float2half(w0[i]); return; }
    i -= NW0;
    if (i < NW1) { o1[i] = __float2half(w1[i]); return; }
    i -= NW1;
    if (i < NW2) { o2[i] = __float2half(w2[i]); return; }
    i -= NW2;
    if (i < NW3) { o3[i] = __float2half(w3[i]); }
}

// ---------------- masked rel-pos bias table ----------------
__global__ void biasm_kernel(const float* __restrict__ rel_table, __half* __restrict__ bm)
{
    int i = blockIdx.x * 256 + threadIdx.x;
    if (i >= 4 * NH * NTOK * NTOK) return;
    int type = i / (NH * NTOK * NTOK);
    int rem  = i % (NH * NTOK * NTOK);
    int h = rem / (NTOK * NTOK);
    int s = rem % (NTOK * NTOK);
    int n = s / NTOK, m = s % NTOK;
    int rn = n / 7, cn = n % 7, rm = m / 7, cm = m % 7;
    int idx = (rn - rm + 6) * 13 + (cn - cm + 6);
    float v = rel_table[idx * NH + h];
    int th = type >> 1, tw = type & 1;
    int rhn = th ? (rn < 4 ? 1 : 2) : 0;
    int rwn = tw ? (cn < 4 ? 1 : 2) : 0;
    int rhm = th ? (rm < 4 ? 1 : 2) : 0;
    int rwm = tw ? (cm < 4 ? 1 : 2) : 0;
    if (rhn * 3 + rwn != rhm * 3 + rwm) v -= 100.f;
    bm[i] = __float2half(v);
}

// ---------------- LayerNorm: one row per warp, float4 I/O ----------------
template<int PERM>
__global__ void __launch_bounds__(256) ln_kernel(
    const float* __restrict__ in, __half* __restrict__ out,
    const float* __restrict__ gam, const float* __restrict__ bet)
{
    const int row = blockIdx.x * 8 + (threadIdx.x >> 5);
    const int lane = threadIdx.x & 31;
    int src;
    if (PERM) {
        int bw = row / NTOK, t = row % NTOK;
        int b = bw >> 6, w = bw & 63;
        int wh = w >> 3, ww = w & 7;
        int r = t / 7, c = t % 7;
        int gh = wh * 7 + r + SHIFT; if (gh >= HW) gh -= HW;
        int gw = ww * 7 + c + SHIFT; if (gw >= HW) gw -= HW;
        src = (b * (HW*HW) + gh * HW + gw) * DIM;
    } else {
        src = row * DIM;
    }
    const int col = lane * 8;
    float4 v0 = *(const float4*)&in[src + col];
    float4 v1 = *(const float4*)&in[src + col + 4];

    float s = v0.x+v0.y+v0.z+v0.w + v1.x+v1.y+v1.z+v1.w;
    float q = v0.x*v0.x+v0.y*v0.y+v0.z*v0.z+v0.w*v0.w
            + v1.x*v1.x+v1.y*v1.y+v1.z*v1.z+v1.w*v1.w;
    #pragma unroll
    for (int o = 16; o > 0; o >>= 1) {
        s += __shfl_xor_sync(0xFFFFFFFFu, s, o);
        q += __shfl_xor_sync(0xFFFFFFFFu, q, o);
    }
    float mu = s * (1.0f/DIM);
    float rstd = rsqrtf(q * (1.0f/DIM) - mu*mu + 1e-5f);

    float4 g0 = *(const float4*)&gam[col], g1 = *(const float4*)&gam[col+4];
    float4 b0 = *(const float4*)&bet[col], b1 = *(const float4*)&bet[col+4];

    uint4 o8;
    ((__half2*)&o8)[0] = __floats2half2_rn((v0.x-mu)*rstd*g0.x+b0.x, (v0.y-mu)*rstd*g0.y+b0.y);
    ((__half2*)&o8)[1] = __floats2half2_rn((v0.z-mu)*rstd*g0.z+b0.z, (v0.w-mu)*rstd*g0.w+b0.w);
    ((__half2*)&o8)[2] = __floats2half2_rn((v1.x-mu)*rstd*g1.x+b1.x, (v1.y-mu)*rstd*g1.y+b1.y);
    ((__half2*)&o8)[3] = __floats2half2_rn((v1.z-mu)*rstd*g1.z+b1.z, (v1.w-mu)*rstd*g1.w+b1.w);
    *(uint4*)&out[(size_t)row * DIM + col] = o8;
}

// ---------------- fp16 GEMM: 64x64 warp tiles, batched fragment loads ------
#define STG_H    (128 * 40)
#define STG_B    (STG_H * 2)
#define GSMEM    (6 * STG_B)   // 61440 B

template<int EPI>
__global__ void __launch_bounds__(128, 2) hgemm(
    const __half* __restrict__ A, const __half* __restrict__ B,
    const float* __restrict__ bias, float* __restrict__ Cf, __half* __restrict__ Ch,
    const float* __restrict__ res, int M, int Nn, int K)
{
    extern __shared__ __half dsm[];

    const int tid = threadIdx.x;
    const int lane = tid & 31, wid = tid >> 5;
    const int wm = wid >> 1, wn = wid & 1;
    const int gid = lane >> 2, tig = lane & 3;
    const int m0 = blockIdx.y * 128, n0 = blockIdx.x * 128;

    const uint32_t sbase = cvta_s(dsm);
    const uint32_t sA = sbase;
    const uint32_t sB = sbase + 3 * STG_B;

    const int lr0 = tid >> 2, lq0 = tid & 3;

    float c[4][8][4];
    #pragma unroll
    for (int i = 0; i < 4; i++)
        #pragma unroll
        for (int j = 0; j < 8; j++)
            #pragma unroll
            for (int r = 0; r < 4; r++) c[i][j][r] = 0.f;

    const int nk = K >> 5;

    const uint32_t a_off = ((uint32_t)(wm * 64 + (lane & 15)) * 40 + (lane >> 4) * 8) * 2;
    const uint32_t b_off = ((uint32_t)(wn * 64 + ((lane >> 4) & 1) * 8 + (lane & 7)) * 40
                           + ((lane >> 3) & 1) * 8) * 2;

    auto issue = [&](int kt, int stg) {
        const size_t kb = (size_t)kt * 32 + lq0 * 8;
        #pragma unroll
        for (int s = 0; s < 4; s++) {
            int row = lr0 + 32 * s;
            uint32_t dA = sA + stg * STG_B + (row * 40 + lq0 * 8) * 2;
            uint32_t dB = sB + stg * STG_B + (row * 40 + lq0 * 8) * 2;
            CP_ASYNC16(dA, &A[(size_t)(m0 + row) * K + kb]);
            CP_ASYNC16(dB, &B[(size_t)(n0 + row) * K + kb]);
        }
        CP_COMMIT();
    };

    issue(0, 0);
    issue(1, 1);

    for (int kt = 0; kt < nk; kt++) {
        const int stg = kt % 3;
        if (kt + 2 < nk) { CP_WAIT1(); } else { CP_WAIT0(); }
        __syncthreads();
        if (kt + 2 < nk) issue(kt + 2, (kt + 2) % 3);

        const uint32_t aS = sA + stg * STG_B + a_off;
        const uint32_t bS = sB + stg * STG_B + b_off;

        // batch ALL fragment loads for both kk halves, then run 64 MMAs
        unsigned af[2][4][4], bf[2][8][2];
        #pragma unroll
        for (int kk = 0; kk < 2; kk++) {
            #pragma unroll
            for (int mt = 0; mt < 4; mt++)
                ldsm_x4(af[kk][mt], aS + (mt * 16 * 40 + kk * 16) * 2);
            #pragma unroll
            for (int p = 0; p < 4; p++) {
                unsigned br[4];
                ldsm_x4(br, bS + (p * 16 * 40 + kk * 16) * 2);
                bf[kk][2*p][0]   = br[0]; bf[kk][2*p][1]   = br[1];
                bf[kk][2*p+1][0] = br[2]; bf[kk][2*p+1][1] = br[3];
            }
        }
        #pragma unroll
        for (int kk = 0; kk < 2; kk++)
            #pragma unroll
            for (int mt = 0; mt < 4; mt++)
                #pragma unroll
                for (int nt = 0; nt < 8; nt++)
                    mma_f16(c[mt][nt], af[kk][mt], bf[kk][nt]);
    }

    // ---------------- epilogue ----------------
    if (EPI == 0 || EPI == 1) {
        __half* sC = dsm;
        const int srow = wm * 16 + gid;
        const int scol = wn * 64 + 2 * tig;
        #pragma unroll
        for (int mt = 0; mt < 4; mt++) {
            __syncthreads();
            #pragma unroll
            for (int nt = 0; nt < 8; nt++) {
                int cb = n0 + wn * 64 + nt * 8 + 2 * tig;
                float bs0 = bias[cb], bs1 = bias[cb + 1];
                float v00 = c[mt][nt][0] + bs0, v01 = c[mt][nt][1] + bs1;
                float v10 = c[mt][nt][2] + bs0, v11 = c[mt][nt][3] + bs1;
                if (EPI == 0) {
                    if (cb < 256) { v00 *= SCALE; v01 *= SCALE; v10 *= SCALE; v11 *= SCALE; }
                } else {
                    const float kk = 0.70710678118654752f;
                    v00 = 0.5f * v00 * (1.f + erff(v00 * kk));
                    v01 = 0.5f * v01 * (1.f + erff(v01 * kk));
                    v10 = 0.5f * v10 * (1.f + erff(v10 * kk));
                    v11 = 0.5f * v11 * (1.f + erff(v11 * kk));
                }
                *(__half2*)&sC[(srow    ) * 136 + scol + nt * 8] = __floats2half2_rn(v00, v01);
                *(__half2*)&sC[(srow + 8) * 136 + scol + nt * 8] = __floats2half2_rn(v10, v11);
            }
            __syncthreads();
            #pragma unroll
            for (int s = 0; s < 4; s++) {
                int idx = tid + s * 128;
                int sr = idx >> 4, c8 = (idx & 15) * 8;
                int grow = m0 + (sr >> 4) * 64 + mt * 16 + (sr & 15);
                uint4 val = *(uint4*)&sC[sr * 136 + c8];
                *(uint4*)&Ch[(size_t)grow * Nn + n0 + c8] = val;
            }
        }
    } else {
        #pragma unroll
        for (int mt = 0; mt < 4; mt++) {
            #pragma unroll
            for (int nt = 0; nt < 8; nt++) {
                int r0 = m0 + wm * 64 + mt * 16 + gid;
                int r1 = r0 + 8;
                int cb = n0 + wn * 64 + nt * 8 + 2 * tig;
                float bs0 = bias[cb], bs1 = bias[cb + 1];
                float v00 = c[mt][nt][0] + bs0, v01 = c[mt][nt][1] + bs1;
                float v10 = c[mt][nt][2] + bs0, v11 = c[mt][nt][3] + bs1;

                if (EPI == 2) {
                    #pragma unroll
                    for (int rr = 0; rr < 2; rr++) {
                        int m = rr ? r1 : r0;
                        float va = rr ? v10 : v00, vb = rr ? v11 : v01;
                        int bw = m / NTOK, t = m % NTOK;
                        int b = bw >> 6, w = bw & 63;
                        int wh = w >> 3, ww = w & 7;
                        int r = t / 7, cc = t % 7;
                        int gh = wh * 7 + r + SHIFT; if (gh >= HW) gh -= HW;
                        int gw = ww * 7 + cc + SHIFT; if (gw >= HW) gw -= HW;
                        size_t dst = (size_t)(b * (HW*HW) + gh * HW + gw) * DIM + cb;
                        float2 rv = *(const float2*)&res[dst];
                        *(float2*)&Cf[dst] = make_float2(va + rv.x, vb + rv.y);
                    }
                } else {
                    size_t d0 = (size_t)r0 * Nn + cb, d1 = (size_t)r1 * Nn + cb;
                    float2 ra = *(const float2*)&res[d0];
                    float2 rb2 = *(const float2*)&res[d1];
                    *(float2*)&Cf[d0] = make_float2(v00 + ra.x, v01 + ra.y);
                    *(float2*)&Cf[d1] = make_float2(v10 + rb2.x, v11 + rb2.y);
                }
            }
        }
    }
}

// ---------------- tensor-core attention (R12 version: scalar frag loads) ---
__global__ void __launch_bounds__(256) attn_kernel(
    const __half* __restrict__ qkv, const __half* __restrict__ biasM,
    __half* __restrict__ out)
{
    __shared__ __half sQ [64][40];
    __shared__ __half sK [56][40];
    __shared__ __half sVT[32][72];
    __shared__ float  sS [64][60];

    __half (*sP)[120] = reinterpret_cast<__half(*)[120]>(sS);

    const int bw = blockIdx.x >> 3;
    const int h  = blockIdx.x & 7;
    const int tid = threadIdx.x, lane = tid & 31, wid = tid >> 5;
    const int gid = lane >> 2, tig = lane & 3;

    const int w = bw & 63;
    const int type = (((w >> 3) == 7) ? 2 : 0) + (((w & 7) == 7) ? 1 : 0);
    const __half* bm = biasM + ((size_t)(type * NH + h)) * (NTOK * NTOK);

    for (int i = tid; i < 32 * 36; i += 256) ((uint32_t*)sVT)[i] = 0;

    for (int i = tid; i < NTOK * 4; i += 256) {
        int n = i >> 2, d8 = (i & 3) * 8;
        size_t basep = (size_t)(bw * NTOK + n) * 768 + h * HD + d8;
        uint4 qu = *(const uint4*)&qkv[basep];
        uint4 ku = *(const uint4*)&qkv[basep + 256];
        uint4 vu = *(const uint4*)&qkv[basep + 512];
        *(uint4*)&sQ[n][d8] = qu;
        *(uint4*)&sK[n][d8] = ku;
        const __half* vh = (const __half*)&vu;
        #pragma unroll
        for (int j = 0; j < 8; j++) sVT[d8 + j][n] = vh[j];
    }
    __syncthreads();

    for (int t = wid; t < 28; t += 8) {
        int mt = t & 3, nt = t >> 2;
        int rb = mt * 16, nb = nt * 8;
        float c[4] = {0.f, 0.f, 0.f, 0.f};
        const uint32_t* qr0 = (const uint32_t*)&sQ[rb + gid][0];
        const uint32_t* qr1 = (const uint32_t*)&sQ[rb + gid + 8][0];
        const uint32_t* kr  = (const uint32_t*)&sK[nb + gid][0];
        #pragma unroll
        for (int ks = 0; ks < 2; ks++) {
            unsigned a[4] = { qr0[8*ks + tig], qr1[8*ks + tig],
                              qr0[8*ks + tig + 4], qr1[8*ks + tig + 4] };
            unsigned b[2] = { kr[8*ks + tig], kr[8*ks + tig + 4] };
            mma_f16(c, a, b);
        }
        sS[rb + gid    ][nb + 2*tig]     = c[0];
        sS[rb + gid    ][nb + 2*tig + 1] = c[1];
        sS[rb + gid + 8][nb + 2*tig]     = c[2];
        sS[rb + gid + 8][nb + 2*tig + 1] = c[3];
    }
    __syncthreads();

    bool has1 = lane < (NTOK - 32);
    int m1c = has1 ? lane + 32 : lane;

    for (int n = wid; n < NTOK; n += 8) {
        float a0 = sS[n][lane] + __half2float(bm[n * NTOK + lane]);
        float a1 = has1 ? (sS[n][m1c] + __half2float(bm[n * NTOK + m1c])) : -1e30f;

        float mx = fmaxf(a0, a1);
        #pragma unroll
        for (int o = 16; o > 0; o >>= 1) mx = fmaxf(mx, __shfl_xor_sync(0xFFFFFFFFu, mx, o));
        float e0 = __expf(a0 - mx);
        float e1 = has1 ? __expf(a1 - mx) : 0.f;
        float sm = e0 + e1;
        #pragma unroll
        for (int o = 16; o > 0; o >>= 1) sm += __shfl_xor_sync(0xFFFFFFFFu, sm, o);
        float inv = 1.f / sm;
        __syncwarp();
        sP[n][lane]      = __float2half(e0 * inv);
        sP[n][lane + 32] = has1 ? __float2half(e1 * inv) : __half(0.f);
    }
    __syncthreads();

    for (int t = wid; t < 16; t += 8) {
        int mt = t & 3, nt = t >> 2;
        int rb = mt * 16, nb = nt * 8;
        float c[4] = {0.f, 0.f, 0.f, 0.f};
        const uint32_t* pr0 = (const uint32_t*)&sP[rb + gid][0];
        const uint32_t* pr1 = (const uint32_t*)&sP[rb + gid + 8][0];
        const uint32_t* vr  = (const uint32_t*)&sVT[nb + gid][0];
        #pragma unroll
        for (int ks = 0; ks < 4; ks++) {
            unsigned a[4] = { pr0[8*ks + tig], pr1[8*ks + tig],
                              pr0[8*ks + tig + 4], pr1[8*ks + tig + 4] };
            unsigned b[2] = { vr[8*ks + tig], vr[8*ks + tig + 4] };
            mma_f16(c, a, b);
        }
        int n0 = rb + gid, n1 = n0 + 8;
        int d = nb + 2 * tig;
        if (n0 < NTOK)
            *(__half2*)&out[(size_t)(bw * NTOK + n0) * 256 + h * HD + d] =
                __floats2half2_rn(c[0], c[1]);
        if (n1 < NTOK)
            *(__half2*)&out[(size_t)(bw * NTOK + n1) * 256 + h * HD + d] =
                __floats2half2_rn(c[2], c[3]);
    }
}

// ---------------- launcher ----------------
extern "C" void kernel_launch(void* const* d_in, const int* in_sizes, int n_in,
                              void* d_out, int out_size)
{
    (void)in_sizes; (void)n_in; (void)out_size;
    const float* x        = (const float*)d_in[0];
    const float* norm1_g  = (const float*)d_in[1];
    const float* norm1_b  = (const float*)d_in[2];
    const float* qkv_w    = (const float*)d_in[3];
    const float* qkv_b    = (const float*)d_in[4];
    const float* rel_tab  = (const float*)d_in[5];
    const float* proj_w   = (const float*)d_in[6];
    const float* proj_b   = (const float*)d_in[7];
    const float* norm2_g  = (const float*)d_in[8];
    const float* norm2_b  = (const float*)d_in[9];
    const float* fc1_w    = (const float*)d_in[10];
    const float* fc1_b    = (const float*)d_in[11];
    const float* fc2_w    = (const float*)d_in[12];
    const float* fc2_b    = (const float*)d_in[13];
    float* out = (float*)d_out;

    __half *p_a, *p_qkv, *p_h1, *p_wqkv, *p_wproj, *p_wfc1, *p_wfc2, *p_biasM;
    float *p_xres;
    cudaGetSymbolAddress((void**)&p_a,     hb_a);
    cudaGetSymbolAddress((void**)&p_qkv,   hb_qkv);
    cudaGetSymbolAddress((void**)&p_h1,    hb_h1);
    cudaGetSymbolAddress((void**)&p_xres,  g_xres);
    cudaGetSymbolAddress((void**)&p_biasM, g_biasM);
    cudaGetSymbolAddress((void**)&p_wqkv,  hw_qkv);
    cudaGetSymbolAddress((void**)&p_wproj, hw_proj);
    cudaGetSymbolAddress((void**)&p_wfc1,  hw_fc1);
    cudaGetSymbolAddress((void**)&p_wfc2,  hw_fc2);

    cudaFuncSetAttribute(hgemm<0>, cudaFuncAttributeMaxDynamicSharedMemorySize, GSMEM);
    cudaFuncSetAttribute(hgemm<1>, cudaFuncAttributeMaxDynamicSharedMemorySize, GSMEM);
    cudaFuncSetAttribute(hgemm<2>, cudaFuncAttributeMaxDynamicSharedMemorySize, GSMEM);
    cudaFuncSetAttribute(hgemm<3>, cudaFuncAttributeMaxDynamicSharedMemorySize, GSMEM);

    const int M = MTOK;

    // #1: all weight conversions
    wconv_all<<<(NW0 + NW1 + NW2 + NW3 + 255)/256, 256>>>(
        qkv_w, p_wqkv, proj_w, p_wproj, fc1_w, p_wfc1, fc2_w, p_wfc2);
    // #2: masked bias table
    biasm_kernel<<<(4*NH*NTOK*NTOK + 255)/256, 256>>>(rel_tab, p_biasM);
    // #3: LN1
    ln_kernel<1><<<M/8, 256>>>(x, p_a, norm1_g, norm1_b);
    // #4 (profiled): qkv gemm
    hgemm<0><<<dim3(768/128, M/128), 128, GSMEM>>>(p_a, p_wqkv, qkv_b, nullptr, p_qkv, nullptr, M, 768, 256);
    // #5: attention
    attn_kernel<<<BW * NH, 256>>>(p_qkv, p_biasM, p_a);
    // #6: proj
    hgemm<2><<<dim3(256/128, M/128), 128, GSMEM>>>(p_a, p_wproj, proj_b, p_xres, nullptr, x, M, 256, 256);
    // #7: LN2
    ln_kernel<0><<<M/8, 256>>>(p_xres, p_a, norm2_g, norm2_b);
    // #8: fc1
    hgemm<1><<<dim3(1024/128, M/128), 128, GSMEM>>>(p_a, p_wfc1, fc1_b, nullptr, p_h1, nullptr, M, 1024, 256);
    // #9: fc2
    hgemm<3><<<dim3(256/128, M/128), 128, GSMEM>>>(p_h1, p_wfc2, fc2_b, out, nullptr, p_xres, M, 256, 1024);
}